// round 14
// baseline (speedup 1.0000x reference)
#include <cuda_runtime.h>
#include <cuda_fp16.h>

#define NU 100000
#define NI 50000
#define NN 150000            // NU + NI
#define NE 3000000
#define DIM 128
#define D4  32               // DIM / 4 (float4 / uint2 chunks per row)

#define SCAN_B 1024
#define SCAN_NB 147          // ceil(NN / 1024) — all blocks co-resident on 148 SMs

// ---- device scratch (allocation-free requirement) ----
// fp16 embedding buffers: [0]=x, [1]=a1, [2]=a2. (a3 is fused into output.)
__device__ uint2 g_h[3][(size_t)NN * D4];
__device__ int    g_deg[NN];
__device__ float  g_inv[NN];
__device__ int    g_off[NN + 1];
__device__ int    g_cur[NN];
__device__ int    g_csr[NE];
__device__ int    g_part[SCAN_NB];
__device__ int    g_base[SCAN_NB];
__device__ int    g_done;
__device__ int    g_ready;
__device__ int    g_is64;

__device__ __forceinline__ __half2 u2h(unsigned u) {
    return *reinterpret_cast<__half2*>(&u);
}

// ---- 0) fused: detect edge dtype (block 0) + zero deg + reset scan flags ----
__global__ void k_detect_zero(const int* __restrict__ ei32) {
    int i = blockIdx.x * blockDim.x + threadIdx.x;
    if (i < NN) g_deg[i] = 0;
    if (i == 0) { g_done = 0; g_ready = 0; }
    if (blockIdx.x == 0) {
        __shared__ int s_or[256];
        int acc = 0;
        for (int j = threadIdx.x; j < 4096; j += 256) acc |= ei32[2 * j + 1];
        s_or[threadIdx.x] = acc;
        __syncthreads();
        for (int d = 128; d > 0; d >>= 1) {
            if (threadIdx.x < d) s_or[threadIdx.x] |= s_or[threadIdx.x + d];
            __syncthreads();
        }
        if (threadIdx.x == 0) g_is64 = (s_or[0] == 0) ? 1 : 0;
    }
}

// ---- 1) init: g_h[0] = fp16(cat(user, item)) ----
__global__ void k_init_emb(const float4* __restrict__ u4,
                           const float4* __restrict__ i4) {
    const int n4 = NN * D4;
    const int u_n4 = NU * D4;
    for (int i = blockIdx.x * blockDim.x + threadIdx.x; i < n4;
         i += gridDim.x * blockDim.x) {
        float4 v = (i < u_n4) ? u4[i] : i4[i - u_n4];
        __half2 a = __floats2half2_rn(v.x, v.y);
        __half2 b = __floats2half2_rn(v.z, v.w);
        uint2 o;
        o.x = *reinterpret_cast<unsigned*>(&a);
        o.y = *reinterpret_cast<unsigned*>(&b);
        g_h[0][i] = o;
    }
}

// ---- 2) degree histogram over dst (dst-only reads, unroll x2) ----
__global__ void k_hist(const void* __restrict__ ei) {
    const int is64 = g_is64;
    const int T = gridDim.x * blockDim.x;
    int e = blockIdx.x * blockDim.x + threadIdx.x;
    if (is64) {
        const long long* d64 = (const long long*)ei + NE;
        for (; e + T < NE; e += 2 * T) {
            int d0 = (int)d64[e];
            int d1 = (int)d64[e + T];
            if ((unsigned)d0 < NN) atomicAdd(&g_deg[d0], 1);
            if ((unsigned)d1 < NN) atomicAdd(&g_deg[d1], 1);
        }
        for (; e < NE; e += T) {
            int d0 = (int)d64[e];
            if ((unsigned)d0 < NN) atomicAdd(&g_deg[d0], 1);
        }
    } else {
        const int* d32 = (const int*)ei + NE;
        for (; e + T < NE; e += 2 * T) {
            int d0 = d32[e];
            int d1 = d32[e + T];
            if ((unsigned)d0 < NN) atomicAdd(&g_deg[d0], 1);
            if ((unsigned)d1 < NN) atomicAdd(&g_deg[d1], 1);
        }
        for (; e < NE; e += T) {
            int d0 = d32[e];
            if ((unsigned)d0 < NN) atomicAdd(&g_deg[d0], 1);
        }
    }
}

// ---- 3) single-kernel ordered exclusive scan (147 co-resident blocks).
//         Last-arriving block scans the partials; others spin on ready flag. ----
__global__ void k_scan_fused() {
    __shared__ int sh[SCAN_B];
    __shared__ int s_last;
    __shared__ int s_base;
    int bid = blockIdx.x;
    int gid = bid * SCAN_B + threadIdx.x;
    int v = (gid < NN) ? g_deg[gid] : 0;
    sh[threadIdx.x] = v;
    __syncthreads();
    for (int d = 1; d < SCAN_B; d <<= 1) {
        int t = (threadIdx.x >= d) ? sh[threadIdx.x - d] : 0;
        __syncthreads();
        sh[threadIdx.x] += t;
        __syncthreads();
    }
    int incl = sh[threadIdx.x];                   // keep in register (sh reused below)
    if (threadIdx.x == 0) {
        g_part[bid] = sh[SCAN_B - 1];
        __threadfence();
        s_last = (atomicAdd(&g_done, 1) == SCAN_NB - 1) ? 1 : 0;
    }
    __syncthreads();
    if (s_last) {
        // block-wide exclusive scan of the 147 block sums
        int pv = (threadIdx.x < SCAN_NB) ? g_part[threadIdx.x] : 0;
        sh[threadIdx.x] = pv;
        __syncthreads();
        for (int d = 1; d < SCAN_B; d <<= 1) {
            int t = (threadIdx.x >= d) ? sh[threadIdx.x - d] : 0;
            __syncthreads();
            sh[threadIdx.x] += t;
            __syncthreads();
        }
        if (threadIdx.x < SCAN_NB) g_base[threadIdx.x] = sh[threadIdx.x] - pv;
        __threadfence();
        if (threadIdx.x == 0) atomicExch(&g_ready, 1);
    }
    if (threadIdx.x == 0) {
        while (atomicAdd(&g_ready, 0) == 0) { }
        s_base = g_base[bid];
    }
    __syncthreads();
    if (gid < NN) {
        int o = s_base + incl - v;                // ordered exclusive offset
        g_off[gid] = o;
        g_cur[gid] = o;
        g_inv[gid] = (v > 0) ? (1.0f / (float)v) : 0.0f;
    }
    if (gid == 0) g_off[NN] = NE;
}

// ---- 4) scatter src indices into CSR slots.
//         Front-batched 4 edges/iter: 8 independent loads, then 4 atomics,
//         then 4 stores — raises MLP on the ATOMG-return critical path. ----
__global__ void k_scatter(const void* __restrict__ ei) {
    const int is64 = g_is64;
    const int T = gridDim.x * blockDim.x;
    const int tid = blockIdx.x * blockDim.x + threadIdx.x;
    int e = tid * 4;
    const int stride = T * 4;
    for (; e + 3 < NE; e += stride) {
        int s0, s1, s2, s3, d0, d1, d2, d3;
        if (is64) {
            const long long* s64 = (const long long*)ei;
            const long long* x64 = s64 + NE;
            s0 = (int)s64[e];     s1 = (int)s64[e + 1];
            s2 = (int)s64[e + 2]; s3 = (int)s64[e + 3];
            d0 = (int)x64[e];     d1 = (int)x64[e + 1];
            d2 = (int)x64[e + 2]; d3 = (int)x64[e + 3];
        } else {
            const int* s32 = (const int*)ei;
            const int* x32 = s32 + NE;
            s0 = s32[e];     s1 = s32[e + 1];
            s2 = s32[e + 2]; s3 = s32[e + 3];
            d0 = x32[e];     d1 = x32[e + 1];
            d2 = x32[e + 2]; d3 = x32[e + 3];
        }
        int p0 = ((unsigned)d0 < NN) ? atomicAdd(&g_cur[d0], 1) : -1;
        int p1 = ((unsigned)d1 < NN) ? atomicAdd(&g_cur[d1], 1) : -1;
        int p2 = ((unsigned)d2 < NN) ? atomicAdd(&g_cur[d2], 1) : -1;
        int p3 = ((unsigned)d3 < NN) ? atomicAdd(&g_cur[d3], 1) : -1;
        if (p0 >= 0 && (unsigned)s0 < NN) g_csr[p0] = s0;
        if (p1 >= 0 && (unsigned)s1 < NN) g_csr[p1] = s1;
        if (p2 >= 0 && (unsigned)s2 < NN) g_csr[p2] = s2;
        if (p3 >= 0 && (unsigned)s3 < NN) g_csr[p3] = s3;
    }
    // tail (NE % 4 == 0 for NE=3M, but keep generic)
    for (; e < NE; ++e) {
        int src, dst;
        if (is64) {
            src = (int)((const long long*)ei)[e];
            dst = (int)((const long long*)ei)[NE + e];
        } else {
            src = ((const int*)ei)[e];
            dst = ((const int*)ei)[NE + e];
        }
        if ((unsigned)dst < NN && (unsigned)src < NN)
            g_csr[atomicAdd(&g_cur[dst], 1)] = src;
    }
}

// ---- helper: accumulate one fp16 chunk (4 halves) into fp32 sums ----
__device__ __forceinline__ void acc4(uint2 v, float& sx, float& sy,
                                     float& sz, float& sw) {
    float2 fa = __half22float2(u2h(v.x));
    float2 fb = __half22float2(u2h(v.y));
    sx += fa.x; sy += fa.y; sz += fb.x; sw += fb.y;
}

// ---- 5) propagation layer. FUSE=1: layer 3 + final combine fused.
//         Warp per node, lane handles 4 dims. Depth-2 HADD2 tree per 4 edges. ----
template<int FUSE>
__global__ void k_layer_t(int in_idx, float4* __restrict__ out4) {
    const uint2* __restrict__ in = g_h[in_idx];

    int warp = (blockIdx.x * blockDim.x + threadIdx.x) >> 5;
    if (warp >= NN) return;
    int lane = threadIdx.x & 31;

    int beg = g_off[warp];
    int end = g_off[warp + 1];

    float sx = 0.f, sy = 0.f, sz = 0.f, sw = 0.f;
    int e = beg;
    for (; e + 3 < end; e += 4) {
        int s0 = g_csr[e];
        int s1 = g_csr[e + 1];
        int s2 = g_csr[e + 2];
        int s3 = g_csr[e + 3];
        uint2 v0 = in[(size_t)s0 * D4 + lane];
        uint2 v1 = in[(size_t)s1 * D4 + lane];
        uint2 v2 = in[(size_t)s2 * D4 + lane];
        uint2 v3 = in[(size_t)s3 * D4 + lane];
        // depth-2 fp16 tree, one fp32 accumulate per 4 edges
        __half2 a = __hadd2(__hadd2(u2h(v0.x), u2h(v1.x)),
                            __hadd2(u2h(v2.x), u2h(v3.x)));
        __half2 b = __hadd2(__hadd2(u2h(v0.y), u2h(v1.y)),
                            __hadd2(u2h(v2.y), u2h(v3.y)));
        float2 fa = __half22float2(a);
        float2 fb = __half22float2(b);
        sx += fa.x; sy += fa.y; sz += fb.x; sw += fb.y;
    }
    for (; e < end; ++e) {                      // tail: exact fp32 adds
        int s = g_csr[e];
        acc4(in[(size_t)s * D4 + lane], sx, sy, sz, sw);
    }

    float idg = g_inv[warp];
    float rx = sx * idg, ry = sy * idg, rz = sz * idg, rw = sw * idg;

    size_t oi = (size_t)warp * D4 + lane;
    if (FUSE) {
        // out = (x + a1 + a2 + a3) / 4 ; x from fp16 g_h[0], a2 == in[oi],
        // a3 == r (registers). All fp16 reads, fp32 accumulate.
        float tx = rx, ty = ry, tz = rz, tw = rw;
        acc4(g_h[0][oi], tx, ty, tz, tw);
        acc4(g_h[1][oi], tx, ty, tz, tw);
        acc4(in[oi],     tx, ty, tz, tw);
        float4 r;
        r.x = tx * 0.25f; r.y = ty * 0.25f; r.z = tz * 0.25f; r.w = tw * 0.25f;
        __stcs(&out4[oi], r);                   // streaming: evict-first, out never re-read
    } else {
        __half2 ha = __floats2half2_rn(rx, ry);
        __half2 hb = __floats2half2_rn(rz, rw);
        uint2 o;
        o.x = *reinterpret_cast<unsigned*>(&ha);
        o.y = *reinterpret_cast<unsigned*>(&hb);
        g_h[in_idx + 1][oi] = o;
    }
}

extern "C" void kernel_launch(void* const* d_in, const int* in_sizes, int n_in,
                              void* d_out, int out_size) {
    const float4* u4  = (const float4*)d_in[0];
    const float4* i4  = (const float4*)d_in[1];
    const void*   ei  = d_in[2];
    float4*       out = (float4*)d_out;

    // CSR build first; init_emb LAST so the gather table is L2-hot for layer 1
    k_detect_zero<<<(NN + 255) / 256, 256>>>((const int*)ei);
    k_hist<<<4096, 256>>>(ei);
    k_scan_fused<<<SCAN_NB, SCAN_B>>>();
    k_scatter<<<4096, 256>>>(ei);
    k_init_emb<<<2048, 256>>>(u4, i4);

    // 3 propagation layers (warp per node); layer 3 fused with final combine
    const int layer_blocks = (NN * 32 + 255) / 256;
    k_layer_t<0><<<layer_blocks, 256>>>(0, out);  // x  -> a1
    k_layer_t<0><<<layer_blocks, 256>>>(1, out);  // a1 -> a2
    k_layer_t<1><<<layer_blocks, 256>>>(2, out);  // a2 -> out (fused)
}

// round 15
// speedup vs baseline: 1.0504x; 1.0504x over previous
#include <cuda_runtime.h>
#include <cuda_fp16.h>

#define NU 100000
#define NI 50000
#define NN 150000            // NU + NI
#define NE 3000000
#define DIM 128
#define D4  32               // DIM / 4 (float4 / uint2 chunks per row)

#define SCAN_B 1024
#define SCAN_NB 147          // ceil(NN / 1024) — all blocks co-resident on 148 SMs

#define SCAT_BLOCKS 4096
#define INIT_BLOCKS 2048

// ---- device scratch (allocation-free requirement) ----
// fp16 embedding buffers: [0]=x, [1]=a1, [2]=a2. (a3 is fused into output.)
__device__ uint2 g_h[3][(size_t)NN * D4];
__device__ int    g_deg[NN];
__device__ float  g_inv[NN];
__device__ int    g_off[NN + 1];
__device__ int    g_cur[NN];
__device__ int    g_csr[NE];
__device__ int    g_part[SCAN_NB];
__device__ int    g_base[SCAN_NB];
__device__ int    g_done;
__device__ int    g_ready;
__device__ int    g_is64;

__device__ __forceinline__ __half2 u2h(unsigned u) {
    return *reinterpret_cast<__half2*>(&u);
}

// ---- per-block dtype detection: int64 edge array has zero high words.
//      Values < NN=150000 < 2^31, so int64 words read as int32 pairs give
//      (lo, 0) — OR of odd words == 0 iff layout is int64. ----
__device__ __forceinline__ int detect_is64_block(const int* ei32) {
    int acc = 0;
    #pragma unroll
    for (int j = 0; j < 2; j++) acc |= ei32[2 * ((threadIdx.x & 31) + 32 * j) + 1];
    // warp-reduce OR (values identical across warps; any warp works)
    #pragma unroll
    for (int d = 16; d > 0; d >>= 1) acc |= __shfl_xor_sync(0xffffffffu, acc, d);
    return (acc == 0) ? 1 : 0;
}

// ---- 0) zero deg + reset scan flags ----
__global__ void k_zero() {
    int i = blockIdx.x * blockDim.x + threadIdx.x;
    if (i < NN) g_deg[i] = 0;
    if (i == 0) { g_done = 0; g_ready = 0; }
}

// ---- 1) degree histogram over dst (dst-only reads, unroll x2);
//         block-local dtype detection, block 0 publishes g_is64 for scatter. ----
__global__ void k_hist(const void* __restrict__ ei) {
    const int is64 = detect_is64_block((const int*)ei);
    if (blockIdx.x == 0 && threadIdx.x == 0) g_is64 = is64;
    const int T = gridDim.x * blockDim.x;
    int e = blockIdx.x * blockDim.x + threadIdx.x;
    if (is64) {
        const long long* d64 = (const long long*)ei + NE;
        for (; e + T < NE; e += 2 * T) {
            int d0 = (int)d64[e];
            int d1 = (int)d64[e + T];
            if ((unsigned)d0 < NN) atomicAdd(&g_deg[d0], 1);
            if ((unsigned)d1 < NN) atomicAdd(&g_deg[d1], 1);
        }
        for (; e < NE; e += T) {
            int d0 = (int)d64[e];
            if ((unsigned)d0 < NN) atomicAdd(&g_deg[d0], 1);
        }
    } else {
        const int* d32 = (const int*)ei + NE;
        for (; e + T < NE; e += 2 * T) {
            int d0 = d32[e];
            int d1 = d32[e + T];
            if ((unsigned)d0 < NN) atomicAdd(&g_deg[d0], 1);
            if ((unsigned)d1 < NN) atomicAdd(&g_deg[d1], 1);
        }
        for (; e < NE; e += T) {
            int d0 = d32[e];
            if ((unsigned)d0 < NN) atomicAdd(&g_deg[d0], 1);
        }
    }
}

// ---- 2) single-kernel ordered exclusive scan (147 co-resident blocks).
//         Last-arriving block scans the partials; others spin on ready flag. ----
__global__ void k_scan_fused() {
    __shared__ int sh[SCAN_B];
    __shared__ int s_last;
    __shared__ int s_base;
    int bid = blockIdx.x;
    int gid = bid * SCAN_B + threadIdx.x;
    int v = (gid < NN) ? g_deg[gid] : 0;
    sh[threadIdx.x] = v;
    __syncthreads();
    for (int d = 1; d < SCAN_B; d <<= 1) {
        int t = (threadIdx.x >= d) ? sh[threadIdx.x - d] : 0;
        __syncthreads();
        sh[threadIdx.x] += t;
        __syncthreads();
    }
    int incl = sh[threadIdx.x];                   // keep in register (sh reused below)
    if (threadIdx.x == 0) {
        g_part[bid] = sh[SCAN_B - 1];
        __threadfence();
        s_last = (atomicAdd(&g_done, 1) == SCAN_NB - 1) ? 1 : 0;
    }
    __syncthreads();
    if (s_last) {
        // block-wide exclusive scan of the 147 block sums
        int pv = (threadIdx.x < SCAN_NB) ? g_part[threadIdx.x] : 0;
        sh[threadIdx.x] = pv;
        __syncthreads();
        for (int d = 1; d < SCAN_B; d <<= 1) {
            int t = (threadIdx.x >= d) ? sh[threadIdx.x - d] : 0;
            __syncthreads();
            sh[threadIdx.x] += t;
            __syncthreads();
        }
        if (threadIdx.x < SCAN_NB) g_base[threadIdx.x] = sh[threadIdx.x] - pv;
        __threadfence();
        if (threadIdx.x == 0) atomicExch(&g_ready, 1);
    }
    if (threadIdx.x == 0) {
        while (atomicAdd(&g_ready, 0) == 0) { }
        s_base = g_base[bid];
    }
    __syncthreads();
    if (gid < NN) {
        int o = s_base + incl - v;                // ordered exclusive offset
        g_off[gid] = o;
        g_cur[gid] = o;
        g_inv[gid] = (v > 0) ? (1.0f / (float)v) : 0.0f;
    }
    if (gid == 0) g_off[NN] = NE;
}

// ---- 3) fused: scatter (blocks [0,SCAT)) + init fp16 embeddings (rest).
//         Both depend only on the scan; scatter is latency-bound (5% issue),
//         so init's streaming work is absorbed nearly for free. ----
__global__ void k_scatter_init(const void* __restrict__ ei,
                               const float4* __restrict__ u4,
                               const float4* __restrict__ i4) {
    if (blockIdx.x < SCAT_BLOCKS) {
        const int is64 = g_is64;
        const int T = SCAT_BLOCKS * blockDim.x;
        for (int e = blockIdx.x * blockDim.x + threadIdx.x; e < NE; e += T) {
            int src, dst;
            if (is64) {
                src = (int)((const long long*)ei)[e];
                dst = (int)((const long long*)ei)[NE + e];
            } else {
                src = ((const int*)ei)[e];
                dst = ((const int*)ei)[NE + e];
            }
            if ((unsigned)dst < NN && (unsigned)src < NN) {
                int pos = atomicAdd(&g_cur[dst], 1);
                g_csr[pos] = src;
            }
        }
    } else {
        const int n4 = NN * D4;
        const int u_n4 = NU * D4;
        const int stride = INIT_BLOCKS * blockDim.x;
        for (int i = (blockIdx.x - SCAT_BLOCKS) * blockDim.x + threadIdx.x;
             i < n4; i += stride) {
            float4 v = (i < u_n4) ? u4[i] : i4[i - u_n4];
            __half2 a = __floats2half2_rn(v.x, v.y);
            __half2 b = __floats2half2_rn(v.z, v.w);
            uint2 o;
            o.x = *reinterpret_cast<unsigned*>(&a);
            o.y = *reinterpret_cast<unsigned*>(&b);
            g_h[0][i] = o;
        }
    }
}

// ---- helper: accumulate one fp16 chunk (4 halves) into fp32 sums ----
__device__ __forceinline__ void acc4(uint2 v, float& sx, float& sy,
                                     float& sz, float& sw) {
    float2 fa = __half22float2(u2h(v.x));
    float2 fb = __half22float2(u2h(v.y));
    sx += fa.x; sy += fa.y; sz += fb.x; sw += fb.y;
}

// ---- 4) propagation layer. FUSE=1: layer 3 + final combine fused.
//         Warp per node, lane handles 4 dims. Depth-2 HADD2 tree per 4 edges. ----
template<int FUSE>
__global__ void k_layer_t(int in_idx, float4* __restrict__ out4) {
    const uint2* __restrict__ in = g_h[in_idx];

    int warp = (blockIdx.x * blockDim.x + threadIdx.x) >> 5;
    if (warp >= NN) return;
    int lane = threadIdx.x & 31;

    int beg = g_off[warp];
    int end = g_off[warp + 1];

    float sx = 0.f, sy = 0.f, sz = 0.f, sw = 0.f;
    int e = beg;
    for (; e + 3 < end; e += 4) {
        int s0 = g_csr[e];
        int s1 = g_csr[e + 1];
        int s2 = g_csr[e + 2];
        int s3 = g_csr[e + 3];
        uint2 v0 = in[(size_t)s0 * D4 + lane];
        uint2 v1 = in[(size_t)s1 * D4 + lane];
        uint2 v2 = in[(size_t)s2 * D4 + lane];
        uint2 v3 = in[(size_t)s3 * D4 + lane];
        // depth-2 fp16 tree, one fp32 accumulate per 4 edges
        __half2 a = __hadd2(__hadd2(u2h(v0.x), u2h(v1.x)),
                            __hadd2(u2h(v2.x), u2h(v3.x)));
        __half2 b = __hadd2(__hadd2(u2h(v0.y), u2h(v1.y)),
                            __hadd2(u2h(v2.y), u2h(v3.y)));
        float2 fa = __half22float2(a);
        float2 fb = __half22float2(b);
        sx += fa.x; sy += fa.y; sz += fb.x; sw += fb.y;
    }
    for (; e < end; ++e) {                      // tail: exact fp32 adds
        int s = g_csr[e];
        acc4(in[(size_t)s * D4 + lane], sx, sy, sz, sw);
    }

    float idg = g_inv[warp];
    float rx = sx * idg, ry = sy * idg, rz = sz * idg, rw = sw * idg;

    size_t oi = (size_t)warp * D4 + lane;
    if (FUSE) {
        // out = (x + a1 + a2 + a3) / 4 ; x from fp16 g_h[0], a2 == in[oi],
        // a3 == r (registers). All fp16 reads, fp32 accumulate.
        float tx = rx, ty = ry, tz = rz, tw = rw;
        acc4(g_h[0][oi], tx, ty, tz, tw);
        acc4(g_h[1][oi], tx, ty, tz, tw);
        acc4(in[oi],     tx, ty, tz, tw);
        float4 r;
        r.x = tx * 0.25f; r.y = ty * 0.25f; r.z = tz * 0.25f; r.w = tw * 0.25f;
        __stcs(&out4[oi], r);                   // streaming: evict-first, out never re-read
    } else {
        __half2 ha = __floats2half2_rn(rx, ry);
        __half2 hb = __floats2half2_rn(rz, rw);
        uint2 o;
        o.x = *reinterpret_cast<unsigned*>(&ha);
        o.y = *reinterpret_cast<unsigned*>(&hb);
        g_h[in_idx + 1][oi] = o;
    }
}

extern "C" void kernel_launch(void* const* d_in, const int* in_sizes, int n_in,
                              void* d_out, int out_size) {
    const float4* u4  = (const float4*)d_in[0];
    const float4* i4  = (const float4*)d_in[1];
    const void*   ei  = d_in[2];
    float4*       out = (float4*)d_out;

    // CSR build: zero, hist(+detect), one-shot scan, fused scatter+init
    k_zero<<<(NN + 255) / 256, 256>>>();
    k_hist<<<4096, 256>>>(ei);
    k_scan_fused<<<SCAN_NB, SCAN_B>>>();
    k_scatter_init<<<SCAT_BLOCKS + INIT_BLOCKS, 256>>>(ei, u4, i4);

    // 3 propagation layers (warp per node); layer 3 fused with final combine
    const int layer_blocks = (NN * 32 + 255) / 256;
    k_layer_t<0><<<layer_blocks, 256>>>(0, out);  // x  -> a1
    k_layer_t<0><<<layer_blocks, 256>>>(1, out);  // a1 -> a2
    k_layer_t<1><<<layer_blocks, 256>>>(2, out);  // a2 -> out (fused)
}